// round 3
// baseline (speedup 1.0000x reference)
#include <cuda_runtime.h>
#include <stdint.h>

#define NN      8192
#define EE      262144
#define IN_NODE 11
#define IN_EDGE 4
#define IN_NF   15     // IN_NODE + IN_EDGE
#define H_NF    4
#define OUT_NF  4
#define EMB_NF  2

// Scratch (no allocations allowed) ------------------------------------------
__device__ float g_agg[NN * IN_EDGE];     // segment-sum result
__device__ float g_emb[NN * EMB_NF];      // node embeddings
__device__ float g_Wf[IN_NF * EMB_NF];    // fused MLP weight [15,2]
__device__ float g_bf[EMB_NF];            // fused MLP bias

// ---------------------------------------------------------------------------
// Kernel 1: zero the aggregation buffer + fuse the (purely affine) MLP.
// emb = node_in @ (W1@W2@We) + (b1@W2@We + b2@We + be)
// ---------------------------------------------------------------------------
__global__ void k_prep(const float* __restrict__ W1, const float* __restrict__ b1,
                       const float* __restrict__ W2, const float* __restrict__ b2,
                       const float* __restrict__ We, const float* __restrict__ be) {
    int tid = blockIdx.x * blockDim.x + threadIdx.x;
    for (int i = tid; i < NN * IN_EDGE; i += gridDim.x * blockDim.x)
        g_agg[i] = 0.0f;

    if (blockIdx.x == 0 && threadIdx.x < 32) {
        int t = threadIdx.x;
        if (t < IN_NF * EMB_NF) {
            int r = t >> 1, c = t & 1;
            float acc = 0.0f;
            for (int a = 0; a < H_NF; a++) {
                float w1 = W1[r * H_NF + a];
                for (int b = 0; b < OUT_NF; b++)
                    acc += w1 * W2[a * OUT_NF + b] * We[b * EMB_NF + c];
            }
            g_Wf[t] = acc;
        } else if (t < IN_NF * EMB_NF + EMB_NF) {
            int c = t - IN_NF * EMB_NF;   // 0 or 1
            float acc = be[c];
            for (int b = 0; b < OUT_NF; b++) {
                float hb = b2[b];
                for (int a = 0; a < H_NF; a++) hb += b1[a] * W2[a * OUT_NF + b];
                acc += hb * We[b * EMB_NF + c];
            }
            g_bf[c] = acc;
        }
    }
}

// ---------------------------------------------------------------------------
// Kernel 2: scatter-add edge_attr into g_agg by source node.
// edge_index materialized as int32 on device; row = first E elements.
// ---------------------------------------------------------------------------
__global__ void k_scatter(const int* __restrict__ edge_index,
                          const float* __restrict__ edge_attr) {
    int e = blockIdx.x * blockDim.x + threadIdx.x;
    if (e >= EE) return;
    int r = edge_index[e];                      // edge_index[0][e]
    float4 a = reinterpret_cast<const float4*>(edge_attr)[e];
    atomicAdd(&g_agg[r * IN_EDGE + 0], a.x);
    atomicAdd(&g_agg[r * IN_EDGE + 1], a.y);
    atomicAdd(&g_agg[r * IN_EDGE + 2], a.z);
    atomicAdd(&g_agg[r * IN_EDGE + 3], a.w);
}

// ---------------------------------------------------------------------------
// Kernel 3: per-node embedding via the fused affine map. Writes g_emb and the
// node_emb section of d_out.
// ---------------------------------------------------------------------------
__global__ void k_emb(const float* __restrict__ node_feats, float* __restrict__ out_emb) {
    int i = blockIdx.x * blockDim.x + threadIdx.x;
    if (i >= NN) return;
    float in[IN_NF];
#pragma unroll
    for (int k = 0; k < IN_NODE; k++) in[k] = node_feats[i * IN_NODE + k];
#pragma unroll
    for (int k = 0; k < IN_EDGE; k++) in[IN_NODE + k] = g_agg[i * IN_EDGE + k];

    float ex = g_bf[0], ey = g_bf[1];
#pragma unroll
    for (int k = 0; k < IN_NF; k++) {
        ex += in[k] * g_Wf[k * EMB_NF + 0];
        ey += in[k] * g_Wf[k * EMB_NF + 1];
    }
    g_emb[i * 2 + 0] = ex;
    g_emb[i * 2 + 1] = ey;
    out_emb[i * 2 + 0] = ex;
    out_emb[i * 2 + 1] = ey;
}

// ---------------------------------------------------------------------------
// Kernel 4: all-pairs adjacency. Each CTA handles 4 rows; each thread handles
// 4 columns per iteration -> one float4 STG per row, emb_j reused 4x.
// ---------------------------------------------------------------------------
__device__ __forceinline__ float fast_sigmoid(float x) {
    float e = __expf(-x);                       // MUFU.EX2
    float r;
    asm("rcp.approx.f32 %0, %1;" : "=f"(r) : "f"(1.0f + e));  // MUFU.RCP
    return r;
}

__global__ void __launch_bounds__(256) k_pair(float* __restrict__ adj) {
    const int i0 = blockIdx.x * 4;
    float2 ei[4];
#pragma unroll
    for (int r = 0; r < 4; r++)
        ei[r] = reinterpret_cast<const float2*>(g_emb)[i0 + r];

    for (int g = threadIdx.x; g < NN / 4; g += blockDim.x) {
        const int j0 = g * 4;
        float2 ej[4];
#pragma unroll
        for (int c = 0; c < 4; c++)
            ej[c] = reinterpret_cast<const float2*>(g_emb)[j0 + c];

#pragma unroll
        for (int r = 0; r < 4; r++) {
            float o[4];
#pragma unroll
            for (int c = 0; c < 4; c++) {
                float dx = ei[r].x - ej[c].x;
                float dy = ei[r].y - ej[c].y;
                float d  = dx * dx + dy * dy;
                float s  = fast_sigmoid(10.0f * d - 1.0f);
                o[c] = (j0 + c == i0 + r) ? 0.0f : s;
            }
            float4 v = make_float4(o[0], o[1], o[2], o[3]);
            reinterpret_cast<float4*>(adj + (size_t)(i0 + r) * NN + j0)[0] = v;
        }
    }
}

// ---------------------------------------------------------------------------
extern "C" void kernel_launch(void* const* d_in, const int* in_sizes, int n_in,
                              void* d_out, int out_size) {
    const float* node_feats = (const float*)d_in[0];
    const int*   edge_index = (const int*)d_in[1];
    const float* edge_attr  = (const float*)d_in[2];
    const float* W1 = (const float*)d_in[3];
    const float* b1 = (const float*)d_in[4];
    const float* W2 = (const float*)d_in[5];
    const float* b2 = (const float*)d_in[6];
    const float* We = (const float*)d_in[7];
    const float* be = (const float*)d_in[8];

    float* adj     = (float*)d_out;                       // [N, N]
    float* out_emb = (float*)d_out + (size_t)NN * NN;     // [N, 2]

    k_prep<<<64, 256>>>(W1, b1, W2, b2, We, be);
    k_scatter<<<EE / 256, 256>>>(edge_index, edge_attr);
    k_emb<<<NN / 256, 256>>>(node_feats, out_emb);
    k_pair<<<NN / 4, 256>>>(adj);
}

// round 4
// speedup vs baseline: 1.0680x; 1.0680x over previous
#include <cuda_runtime.h>
#include <stdint.h>

#define NN      8192
#define EE      262144
#define IN_NODE 11
#define IN_EDGE 4
#define IN_NF   15
#define H_NF    4
#define OUT_NF  4
#define EMB_NF  2

// Scratch -------------------------------------------------------------------
// Invariant: g_accx/g_accy are all-zero at entry of every kernel_launch call.
// (Zero-initialized at module load; k_emb re-zeroes them after consuming.)
__device__ float g_accx[NN];
__device__ float g_accy[NN];
__device__ float g_emb2[NN * EMB_NF];

// M[a][c] = sum_b W2[a][b] * We[b][c]   (4x2 intermediate, computed per thread)
__device__ __forceinline__ void fuse_W2We(const float* __restrict__ W2,
                                          const float* __restrict__ We,
                                          float M[H_NF][EMB_NF]) {
#pragma unroll
    for (int a = 0; a < H_NF; a++) {
#pragma unroll
        for (int c = 0; c < EMB_NF; c++) {
            float acc = 0.0f;
#pragma unroll
            for (int b = 0; b < OUT_NF; b++)
                acc += __ldg(&W2[a * OUT_NF + b]) * __ldg(&We[b * EMB_NF + c]);
            M[a][c] = acc;
        }
    }
}

// ---------------------------------------------------------------------------
// Kernel 1: scatter. Each edge adds edge_attr @ Wf_edge (2 values) into the
// per-node embedding accumulator. 2 atomics/edge instead of 4.
// ---------------------------------------------------------------------------
__global__ void __launch_bounds__(256) k_scatter(
        const int* __restrict__ edge_index, const float* __restrict__ edge_attr,
        const float* __restrict__ W1, const float* __restrict__ W2,
        const float* __restrict__ We) {
    float M[H_NF][EMB_NF];
    fuse_W2We(W2, We, M);
    // wfe[r][c] = sum_a W1[11+r][a] * M[a][c]
    float wfe[IN_EDGE][EMB_NF];
#pragma unroll
    for (int r = 0; r < IN_EDGE; r++)
#pragma unroll
        for (int c = 0; c < EMB_NF; c++) {
            float acc = 0.0f;
#pragma unroll
            for (int a = 0; a < H_NF; a++)
                acc += __ldg(&W1[(IN_NODE + r) * H_NF + a]) * M[a][c];
            wfe[r][c] = acc;
        }

    int e = blockIdx.x * blockDim.x + threadIdx.x;
    if (e >= EE) return;
    int rr = edge_index[e];                       // edge_index[0][e] (int32)
    float4 a = reinterpret_cast<const float4*>(edge_attr)[e];
    float cx = a.x * wfe[0][0] + a.y * wfe[1][0] + a.z * wfe[2][0] + a.w * wfe[3][0];
    float cy = a.x * wfe[0][1] + a.y * wfe[1][1] + a.z * wfe[2][1] + a.w * wfe[3][1];
    atomicAdd(&g_accx[rr], cx);
    atomicAdd(&g_accy[rr], cy);
}

// ---------------------------------------------------------------------------
// Kernel 2: per-node embedding = node_feats @ Wf_node + bias + edge-acc.
// Re-zeroes the accumulator (maintains the entry invariant for the next call).
// ---------------------------------------------------------------------------
__global__ void __launch_bounds__(256) k_emb(
        const float* __restrict__ node_feats,
        const float* __restrict__ W1, const float* __restrict__ b1,
        const float* __restrict__ W2, const float* __restrict__ b2,
        const float* __restrict__ We, const float* __restrict__ be,
        float* __restrict__ out_emb) {
    float M[H_NF][EMB_NF];
    fuse_W2We(W2, We, M);
    float wfn[IN_NODE][EMB_NF];
#pragma unroll
    for (int k = 0; k < IN_NODE; k++)
#pragma unroll
        for (int c = 0; c < EMB_NF; c++) {
            float acc = 0.0f;
#pragma unroll
            for (int a = 0; a < H_NF; a++)
                acc += __ldg(&W1[k * H_NF + a]) * M[a][c];
            wfn[k][c] = acc;
        }
    // bias: bf[c] = be[c] + sum_b (b2[b] + sum_a b1[a] W2[a][b]) * We[b][c]
    float bf[EMB_NF];
#pragma unroll
    for (int c = 0; c < EMB_NF; c++) {
        float acc = __ldg(&be[c]);
#pragma unroll
        for (int b = 0; b < OUT_NF; b++) {
            float hb = __ldg(&b2[b]);
#pragma unroll
            for (int a = 0; a < H_NF; a++)
                hb += __ldg(&b1[a]) * __ldg(&W2[a * OUT_NF + b]);
            acc += hb * __ldg(&We[b * EMB_NF + c]);
        }
        bf[c] = acc;
    }

    int i = blockIdx.x * blockDim.x + threadIdx.x;
    if (i >= NN) return;
    float ex = bf[0] + g_accx[i];
    float ey = bf[1] + g_accy[i];
#pragma unroll
    for (int k = 0; k < IN_NODE; k++) {
        float nf = node_feats[i * IN_NODE + k];
        ex += nf * wfn[k][0];
        ey += nf * wfn[k][1];
    }
    g_emb2[i * 2 + 0] = ex;
    g_emb2[i * 2 + 1] = ey;
    out_emb[i * 2 + 0] = ex;
    out_emb[i * 2 + 1] = ey;
    g_accx[i] = 0.0f;       // restore invariant for next call
    g_accy[i] = 0.0f;
}

// ---------------------------------------------------------------------------
// Kernel 3: all-pairs adjacency. 4 rows/CTA, 4 cols/thread/iter, no diagonal
// predicate in the hot loop (fixed after a barrier), streaming float4 stores.
// sigmoid(10d-1) = 1 / (1 + 2^(-10*log2(e)*d + log2(e)))
// ---------------------------------------------------------------------------
#define NEG10_LOG2E  (-14.4269504088896341f)
#define LOG2E         (1.44269504088896341f)

__global__ void __launch_bounds__(256) k_pair(float* __restrict__ adj) {
    const int i0 = blockIdx.x * 4;
    float2 ei[4];
#pragma unroll
    for (int r = 0; r < 4; r++)
        ei[r] = reinterpret_cast<const float2*>(g_emb2)[i0 + r];

    for (int g = threadIdx.x; g < NN / 4; g += blockDim.x) {
        const int j0 = g * 4;
        float2 ej[4];
#pragma unroll
        for (int c = 0; c < 4; c++)
            ej[c] = reinterpret_cast<const float2*>(g_emb2)[j0 + c];

#pragma unroll
        for (int r = 0; r < 4; r++) {
            float o[4];
#pragma unroll
            for (int c = 0; c < 4; c++) {
                float dx = ei[r].x - ej[c].x;
                float dy = ei[r].y - ej[c].y;
                float d  = fmaf(dy, dy, dx * dx);
                float e  = exp2f(fmaf(d, NEG10_LOG2E, LOG2E));  // MUFU.EX2
                float s;
                asm("rcp.approx.f32 %0, %1;" : "=f"(s) : "f"(1.0f + e));
                o[c] = s;
            }
            float4 v = make_float4(o[0], o[1], o[2], o[3]);
            __stcs(reinterpret_cast<float4*>(adj + (size_t)(i0 + r) * NN + j0), v);
        }
    }

    __syncthreads();
    if (threadIdx.x < 4) {
        int i = i0 + threadIdx.x;
        adj[(size_t)i * NN + i] = 0.0f;
    }
}

// ---------------------------------------------------------------------------
extern "C" void kernel_launch(void* const* d_in, const int* in_sizes, int n_in,
                              void* d_out, int out_size) {
    const float* node_feats = (const float*)d_in[0];
    const int*   edge_index = (const int*)d_in[1];
    const float* edge_attr  = (const float*)d_in[2];
    const float* W1 = (const float*)d_in[3];
    const float* b1 = (const float*)d_in[4];
    const float* W2 = (const float*)d_in[5];
    const float* b2 = (const float*)d_in[6];
    const float* We = (const float*)d_in[7];
    const float* be = (const float*)d_in[8];

    float* adj     = (float*)d_out;                       // [N, N]
    float* out_emb = (float*)d_out + (size_t)NN * NN;     // [N, 2]

    k_scatter<<<EE / 256, 256>>>(edge_index, edge_attr, W1, W2, We);
    k_emb<<<NN / 256, 256>>>(node_feats, W1, b1, W2, b2, We, be, out_emb);
    k_pair<<<NN / 4, 256>>>(adj);
}